// round 2
// baseline (speedup 1.0000x reference)
#include <cuda_runtime.h>

#define B_  2
#define L_  2048
#define D_  1024
#define H_  16
#define DH_ 64
#define N3_ 3072
#define MT_ (B_*L_)          // 4096
#define SCALE_ 0.125f        // 64^-0.5

// scratch (allocation-free rule: device globals)
__device__ float g_qkv[MT_ * (size_t)N3_];   // 50 MB
__device__ float g_z[MT_ * (size_t)D_];      // 16 MB

// ---------------------------------------------------------------------------
// SGEMM: C[M,N] = A[M,K] @ B[K,N] (+bias). 128x128x8 tiles, 256 thr, 8x8/thr.
// ---------------------------------------------------------------------------
template<bool BIAS>
__global__ __launch_bounds__(256, 2)
void sgemm128(const float* __restrict__ A, const float* __restrict__ Bm,
              const float* __restrict__ bias, float* __restrict__ C,
              int M, int N, int K)
{
    __shared__ float As[8][132];   // transposed: As[k][m]
    __shared__ float Bs[8][132];   // Bs[k][n]

    const int tid  = threadIdx.x;
    const int row0 = blockIdx.y * 128;
    const int col0 = blockIdx.x * 128;
    const int ty = tid >> 4, tx = tid & 15;
    const int y0 = ty * 8, x0 = tx * 8;

    const int aRow = tid >> 1;          // 0..127
    const int aCol = (tid & 1) * 4;     // 0 / 4
    const int bRow = tid >> 5;          // 0..7
    const int bCol = (tid & 31) * 4;    // 0..124

    float acc[8][8];
    #pragma unroll
    for (int i = 0; i < 8; i++)
        #pragma unroll
        for (int j = 0; j < 8; j++) acc[i][j] = 0.f;

    for (int k0 = 0; k0 < K; k0 += 8) {
        float4 av = *(const float4*)&A[(size_t)(row0 + aRow) * K + k0 + aCol];
        float4 bv = *(const float4*)&Bm[(size_t)(k0 + bRow) * N + col0 + bCol];
        As[aCol + 0][aRow] = av.x;
        As[aCol + 1][aRow] = av.y;
        As[aCol + 2][aRow] = av.z;
        As[aCol + 3][aRow] = av.w;
        *(float4*)&Bs[bRow][bCol] = bv;
        __syncthreads();

        #pragma unroll
        for (int k = 0; k < 8; k++) {
            float a[8], b[8];
            *(float4*)&a[0] = *(const float4*)&As[k][y0];
            *(float4*)&a[4] = *(const float4*)&As[k][y0 + 4];
            *(float4*)&b[0] = *(const float4*)&Bs[k][x0];
            *(float4*)&b[4] = *(const float4*)&Bs[k][x0 + 4];
            #pragma unroll
            for (int i = 0; i < 8; i++)
                #pragma unroll
                for (int j = 0; j < 8; j++)
                    acc[i][j] = fmaf(a[i], b[j], acc[i][j]);
        }
        __syncthreads();
    }

    #pragma unroll
    for (int i = 0; i < 8; i++) {
        size_t crow = (size_t)(row0 + y0 + i) * N + col0 + x0;
        #pragma unroll
        for (int j = 0; j < 8; j += 4) {
            float4 v;
            v.x = acc[i][j + 0]; v.y = acc[i][j + 1];
            v.z = acc[i][j + 2]; v.w = acc[i][j + 3];
            if (BIAS) {
                const float4 bb = *(const float4*)&bias[col0 + x0 + j];
                v.x += bb.x; v.y += bb.y; v.z += bb.z; v.w += bb.w;
            }
            *(float4*)&C[crow + j] = v;
        }
    }
}

// ---------------------------------------------------------------------------
// Flash attention with post-softmax multiplicative mask + renormalization.
// One block = 64 query rows for one (b,h). 256 threads, 4x4 frag per thread.
//   out = sum(e^{s-m}*mask*v) / (sum(e^{s-m}*mask) + eps*sum(e^{s-m}))
// smem layouts transposed so both gemms use LDS.128 on both operands.
// ---------------------------------------------------------------------------
__global__ __launch_bounds__(256)
void attn_kernel(const float* __restrict__ qkv, const float* __restrict__ mask,
                 float* __restrict__ z)
{
    extern __shared__ float smem[];
    float* Qt = smem;             // [64][68]  Qt[d][i]
    float* Kt = Qt + 64 * 68;     // [64][68]  Kt[d][j]
    float* Vs = Kt + 64 * 68;     // [64][68]  Vs[j][d]
    float* Pt = Vs + 64 * 68;     // [64][68]  Pt[j][i]

    const int tid = threadIdx.x;
    const int b = blockIdx.y >> 4;
    const int h = blockIdx.y & 15;
    const int qi0 = blockIdx.x * 64;
    const int ti = tid >> 4, tj = tid & 15;
    const int i0 = ti * 4, j0 = tj * 4;     // j0 doubles as d0 in PV/epilogue

    const size_t qrow = (size_t)b * L_ + qi0;
    const int qcol = h * 64;

    // load Q tile, pre-scaled, transposed
    for (int e = tid; e < 64 * 16; e += 256) {
        int r = e >> 4, d = (e & 15) * 4;
        float4 v = *(const float4*)&qkv[(qrow + r) * N3_ + qcol + d];
        Qt[(d + 0) * 68 + r] = v.x * SCALE_;
        Qt[(d + 1) * 68 + r] = v.y * SCALE_;
        Qt[(d + 2) * 68 + r] = v.z * SCALE_;
        Qt[(d + 3) * 68 + r] = v.w * SCALE_;
    }

    float acc[4][4];
    #pragma unroll
    for (int i = 0; i < 4; i++)
        #pragma unroll
        for (int j = 0; j < 4; j++) acc[i][j] = 0.f;
    float mprev[4] = {-1e30f, -1e30f, -1e30f, -1e30f};
    float se[4] = {0.f, 0.f, 0.f, 0.f};       // unmasked exp-sum
    float sm_[4] = {0.f, 0.f, 0.f, 0.f};      // masked exp-sum

    for (int kt = 0; kt < L_ / 64; kt++) {
        const int kj0 = kt * 64;
        const size_t krow = (size_t)b * L_ + kj0;
        __syncthreads();   // prior PV done before overwriting K/V/P tiles
        for (int e = tid; e < 64 * 16; e += 256) {
            int r = e >> 4, d = (e & 15) * 4;
            float4 kv = *(const float4*)&qkv[(krow + r) * N3_ + 1024 + qcol + d];
            Kt[(d + 0) * 68 + r] = kv.x;
            Kt[(d + 1) * 68 + r] = kv.y;
            Kt[(d + 2) * 68 + r] = kv.z;
            Kt[(d + 3) * 68 + r] = kv.w;
            float4 vv = *(const float4*)&qkv[(krow + r) * N3_ + 2048 + qcol + d];
            *(float4*)&Vs[r * 68 + d] = vv;
        }
        __syncthreads();

        // S = (Q*scale) @ K^T, 4x4 fragment
        float s[4][4];
        #pragma unroll
        for (int i = 0; i < 4; i++)
            #pragma unroll
            for (int j = 0; j < 4; j++) s[i][j] = 0.f;
        #pragma unroll 8
        for (int d = 0; d < 64; d++) {
            float qa[4], kb[4];
            *(float4*)qa = *(const float4*)&Qt[d * 68 + i0];
            *(float4*)kb = *(const float4*)&Kt[d * 68 + j0];
            #pragma unroll
            for (int i = 0; i < 4; i++)
                #pragma unroll
                for (int j = 0; j < 4; j++)
                    s[i][j] = fmaf(qa[i], kb[j], s[i][j]);
        }

        // row max across the 16 tj-lanes (lane%16 == tj within each half-warp)
        float rmax[4];
        #pragma unroll
        for (int i = 0; i < 4; i++)
            rmax[i] = fmaxf(fmaxf(s[i][0], s[i][1]), fmaxf(s[i][2], s[i][3]));
        #pragma unroll
        for (int off = 8; off >= 1; off >>= 1)
            #pragma unroll
            for (int i = 0; i < 4; i++)
                rmax[i] = fmaxf(rmax[i], __shfl_xor_sync(0xffffffffu, rmax[i], off));

        float corr[4], pe[4], pm[4];
        #pragma unroll
        for (int i = 0; i < 4; i++) {
            float mnew = fmaxf(mprev[i], rmax[i]);
            corr[i] = __expf(mprev[i] - mnew);
            mprev[i] = mnew;
            float4 mk = *(const float4*)&mask[((size_t)b * L_ + qi0 + i0 + i) * L_ + kj0 + j0];
            float p0 = __expf(s[i][0] - mnew);
            float p1 = __expf(s[i][1] - mnew);
            float p2 = __expf(s[i][2] - mnew);
            float p3 = __expf(s[i][3] - mnew);
            float q0 = p0 * mk.x, q1 = p1 * mk.y, q2 = p2 * mk.z, q3 = p3 * mk.w;
            pe[i] = (p0 + p1) + (p2 + p3);
            pm[i] = (q0 + q1) + (q2 + q3);
            Pt[(j0 + 0) * 68 + i0 + i] = q0;
            Pt[(j0 + 1) * 68 + i0 + i] = q1;
            Pt[(j0 + 2) * 68 + i0 + i] = q2;
            Pt[(j0 + 3) * 68 + i0 + i] = q3;
        }
        #pragma unroll
        for (int off = 8; off >= 1; off >>= 1)
            #pragma unroll
            for (int i = 0; i < 4; i++) {
                pe[i] += __shfl_xor_sync(0xffffffffu, pe[i], off);
                pm[i] += __shfl_xor_sync(0xffffffffu, pm[i], off);
            }
        #pragma unroll
        for (int i = 0; i < 4; i++) {
            se[i]  = se[i]  * corr[i] + pe[i];
            sm_[i] = sm_[i] * corr[i] + pm[i];
            #pragma unroll
            for (int j = 0; j < 4; j++) acc[i][j] *= corr[i];
        }
        __syncthreads();   // Pt visible to all

        // acc += P_masked @ V
        #pragma unroll 8
        for (int j = 0; j < 64; j++) {
            float pa[4], vb[4];
            *(float4*)pa = *(const float4*)&Pt[j * 68 + i0];
            *(float4*)vb = *(const float4*)&Vs[j * 68 + j0];
            #pragma unroll
            for (int i = 0; i < 4; i++)
                #pragma unroll
                for (int jj = 0; jj < 4; jj++)
                    acc[i][jj] = fmaf(pa[i], vb[jj], acc[i][jj]);
        }
    }

    // epilogue: renormalize and write z[b, l, h, dh]
    #pragma unroll
    for (int i = 0; i < 4; i++) {
        float inv = 1.0f / (sm_[i] + 1e-10f * se[i] + 1e-30f);
        float4 o;
        o.x = acc[i][0] * inv; o.y = acc[i][1] * inv;
        o.z = acc[i][2] * inv; o.w = acc[i][3] * inv;
        *(float4*)&z[((size_t)b * L_ + qi0 + i0 + i) * D_ + qcol + j0] = o;
    }
}

// ---------------------------------------------------------------------------
extern "C" void kernel_launch(void* const* d_in, const int* in_sizes, int n_in,
                              void* d_out, int out_size)
{
    const float* x    = (const float*)d_in[0];
    const float* mask = (const float*)d_in[1];
    const float* Wqkv = (const float*)d_in[2];
    const float* Wout = (const float*)d_in[3];
    const float* bout = (const float*)d_in[4];
    float* out = (float*)d_out;

    float *qkvp, *zp;
    cudaGetSymbolAddress((void**)&qkvp, g_qkv);
    cudaGetSymbolAddress((void**)&zp, g_z);

    // 1) QKV projection: [4096,1024] @ [1024,3072]
    sgemm128<false><<<dim3(N3_ / 128, MT_ / 128), 256>>>(x, Wqkv, nullptr, qkvp,
                                                         MT_, N3_, D_);
    // 2) masked flash attention
    const int smem_bytes = 4 * 64 * 68 * (int)sizeof(float);  // 69632
    cudaFuncSetAttribute(attn_kernel, cudaFuncAttributeMaxDynamicSharedMemorySize,
                         smem_bytes);
    attn_kernel<<<dim3(L_ / 64, B_ * H_), 256, smem_bytes>>>(qkvp, mask, zp);

    // 3) output projection + bias: [4096,1024] @ [1024,1024]
    sgemm128<true><<<dim3(D_ / 128, MT_ / 128), 256>>>(zp, Wout, bout, out,
                                                       MT_, D_, D_);
}

// round 3
// speedup vs baseline: 3.1470x; 3.1470x over previous
#include <cuda_runtime.h>
#include <stdint.h>

#define B_   2
#define L_   2048
#define D_   1024
#define H_   16
#define N3_  3072
#define MT_  4096
#define LOG2E 1.4426950408889634f

// scratch (allocation-free rule: device globals)
__device__ float g_qkv[(size_t)MT_ * N3_];   // tf32-rounded qkv
__device__ float g_z[(size_t)MT_ * D_];      // tf32-rounded attn output
__device__ float g_xr[(size_t)MT_ * D_];     // tf32-rounded x
__device__ float g_wq[(size_t)D_ * N3_];     // tf32-rounded W_qkv
__device__ float g_wo[(size_t)D_ * D_];      // tf32-rounded W_out

__device__ __forceinline__ float to_tf32(float x) {
    uint32_t u; asm("cvt.rna.tf32.f32 %0, %1;" : "=r"(u) : "f"(x));
    return __uint_as_float(u);
}

__device__ __forceinline__ void mma8(float* d, const uint32_t* a, const uint32_t* b) {
    asm volatile(
        "mma.sync.aligned.m16n8k8.row.col.f32.tf32.tf32.f32 "
        "{%0,%1,%2,%3}, {%4,%5,%6,%7}, {%8,%9}, {%0,%1,%2,%3};\n"
        : "+f"(d[0]), "+f"(d[1]), "+f"(d[2]), "+f"(d[3])
        : "r"(a[0]), "r"(a[1]), "r"(a[2]), "r"(a[3]), "r"(b[0]), "r"(b[1]));
}

// fast exp on FMA/ALU pipes (avoids the MUFU throughput wall). x <= 0 here.
__device__ __forceinline__ float fexp(float x) {
    x = fmaxf(x, -80.0f);
    float t = fmaf(x, LOG2E, 12582912.0f);     // round to int in mantissa
    float n = t - 12582912.0f;
    float f = fmaf(x, LOG2E, -n);              // f in [-0.5, 0.5]
    float p = 1.3333558e-3f;                   // 2^f Taylor/minimax deg 5
    p = fmaf(p, f, 9.6181291e-3f);
    p = fmaf(p, f, 5.5504109e-2f);
    p = fmaf(p, f, 2.4022651e-1f);
    p = fmaf(p, f, 6.9314718e-1f);
    p = fmaf(p, f, 1.0f);
    int ni = __float_as_int(t) - 0x4B400000;   // integer exponent n
    return __int_as_float(__float_as_int(p) + (ni << 23));
}

// ---------------------------------------------------------------------------
// tf32 pre-rounding pass
// ---------------------------------------------------------------------------
__global__ void tf32_round(const float4* __restrict__ in, float4* __restrict__ out, int n4) {
    int i = blockIdx.x * 256 + threadIdx.x;
    if (i < n4) {
        float4 v = in[i];
        v.x = to_tf32(v.x); v.y = to_tf32(v.y);
        v.z = to_tf32(v.z); v.w = to_tf32(v.w);
        out[i] = v;
    }
}

// ---------------------------------------------------------------------------
// tf32 mma GEMM: C[M,N] = A[M,K] @ B[K,N] (+bias, optional tf32-round of out)
// 128x128 tile, K-chunk 32, 8 warps as 2(m) x 4(n), warp tile 64x32.
// A,B must already be tf32-rounded values stored as fp32.
// ---------------------------------------------------------------------------
template<bool BIAS, bool ROUND>
__global__ __launch_bounds__(256)
void mma_gemm(const float* __restrict__ A, const float* __restrict__ Bm,
              const float* __restrict__ bias, float* __restrict__ C,
              int M, int N, int K)
{
    __shared__ float As[128][36];   // [m][k], pad 36 -> conflict-free frags
    __shared__ float Bs[32][136];   // [k][n], pad 136 -> conflict-free frags

    const int tid  = threadIdx.x;
    const int w    = tid >> 5, lane = tid & 31;
    const int g    = lane >> 2, tg = lane & 3;
    const int wm   = (w >> 2) * 64;        // warp m offset (2 rows of warps)
    const int wn   = (w & 3) * 32;         // warp n offset (4 cols of warps)
    const int row0 = blockIdx.y * 128, col0 = blockIdx.x * 128;

    float acc[16][4];
    #pragma unroll
    for (int i = 0; i < 16; i++)
        #pragma unroll
        for (int j = 0; j < 4; j++) acc[i][j] = 0.f;

    for (int k0 = 0; k0 < K; k0 += 32) {
        __syncthreads();
        #pragma unroll
        for (int i = 0; i < 4; i++) {
            int id = tid + 256 * i;
            int r = id >> 3, kc = (id & 7) * 4;          // A: 128 x 32
            float4 v = *(const float4*)&A[(size_t)(row0 + r) * K + k0 + kc];
            *(float4*)&As[r][kc] = v;
            int rb = id >> 5, nc = (id & 31) * 4;        // B: 32 x 128
            float4 u = *(const float4*)&Bm[(size_t)(k0 + rb) * N + col0 + nc];
            *(float4*)&Bs[rb][nc] = u;
        }
        __syncthreads();

        #pragma unroll
        for (int k8 = 0; k8 < 4; k8++) {
            const int kk = k8 * 8;
            uint32_t a[4][4], b[4][2];
            #pragma unroll
            for (int mt = 0; mt < 4; mt++) {
                const int m = wm + mt * 16;
                a[mt][0] = __float_as_uint(As[m + g    ][kk + tg]);
                a[mt][1] = __float_as_uint(As[m + g + 8][kk + tg]);
                a[mt][2] = __float_as_uint(As[m + g    ][kk + tg + 4]);
                a[mt][3] = __float_as_uint(As[m + g + 8][kk + tg + 4]);
            }
            #pragma unroll
            for (int nt = 0; nt < 4; nt++) {
                const int n = wn + nt * 8;
                b[nt][0] = __float_as_uint(Bs[kk + tg    ][n + g]);
                b[nt][1] = __float_as_uint(Bs[kk + tg + 4][n + g]);
            }
            #pragma unroll
            for (int mt = 0; mt < 4; mt++)
                #pragma unroll
                for (int nt = 0; nt < 4; nt++)
                    mma8(acc[mt * 4 + nt], a[mt], b[nt]);
        }
    }

    // C frag: c0=(g,2tg) c1=(g,2tg+1) c2=(g+8,2tg) c3=(g+8,2tg+1)
    #pragma unroll
    for (int mt = 0; mt < 4; mt++) {
        #pragma unroll
        for (int nt = 0; nt < 4; nt++) {
            int r = row0 + wm + mt * 16 + g;
            int c = col0 + wn + nt * 8 + 2 * tg;
            float v0 = acc[mt * 4 + nt][0], v1 = acc[mt * 4 + nt][1];
            float v2 = acc[mt * 4 + nt][2], v3 = acc[mt * 4 + nt][3];
            if (BIAS) {
                float b0 = bias[c], b1 = bias[c + 1];
                v0 += b0; v1 += b1; v2 += b0; v3 += b1;
            }
            if (ROUND) {
                v0 = to_tf32(v0); v1 = to_tf32(v1);
                v2 = to_tf32(v2); v3 = to_tf32(v3);
            }
            *(float2*)&C[(size_t)r * N + c]       = make_float2(v0, v1);
            *(float2*)&C[(size_t)(r + 8) * N + c] = make_float2(v2, v3);
        }
    }
}

// ---------------------------------------------------------------------------
// Flash attention (tf32 mma) with post-softmax multiplicative mask + renorm.
//   out = sum(e^{s-m}*mask*v) / (sum(e^{s-m}*mask) + eps*sum(e^{s-m}))
// Block: 128 q-rows for one (b,h); 8 warps, warp owns 16 q-rows (m16 x n64),
// so online softmax is fully warp-local. Tj = 64 keys per iteration.
// ---------------------------------------------------------------------------
#define QS_OFF 0            // [128][68]
#define KS_OFF 8704         // [64][68]
#define VS_OFF 13056        // [64][72]
#define PS_OFF 17664        // [128][68]
#define ATTN_SMEM (26368 * 4)

__global__ __launch_bounds__(256)
void attn_mma(const float* __restrict__ qkv, const float* __restrict__ mask,
              float* __restrict__ z)
{
    extern __shared__ float sm[];
    float* Qs = sm + QS_OFF;   // Qs[m][d]  stride 68
    float* Ks = sm + KS_OFF;   // Ks[j][d]  stride 68
    float* Vs = sm + VS_OFF;   // Vs[j][d]  stride 72
    float* Ps = sm + PS_OFF;   // Ps[m][j]  stride 68 (warp-private rows)

    const int tid = threadIdx.x;
    const int w = tid >> 5, lane = tid & 31;
    const int g = lane >> 2, tg = lane & 3;
    const int m0 = w * 16;                       // this warp's q-row base
    const int bb = blockIdx.y >> 4;
    const int h  = blockIdx.y & 15;
    const int qi0 = blockIdx.x * 128;
    const size_t tok0 = (size_t)bb * L_ + qi0;
    const int hc = h * 64;

    // load Q tile: 128 x 64
    #pragma unroll
    for (int i = 0; i < 8; i++) {
        int id = tid + 256 * i;
        int r = id >> 4, dc = (id & 15) * 4;
        float4 v = *(const float4*)&qkv[(tok0 + r) * N3_ + hc + dc];
        *(float4*)&Qs[r * 68 + dc] = v;
    }

    float acc[8][4];
    #pragma unroll
    for (int i = 0; i < 8; i++)
        #pragma unroll
        for (int j = 0; j < 4; j++) acc[i][j] = 0.f;
    float mp0 = -1e30f, mp1 = -1e30f;
    float se0 = 0.f, se1 = 0.f, sq0 = 0.f, sq1 = 0.f;

    const float* mrow0 = mask + (tok0 + m0 + g) * L_ + 2 * tg;
    const float* mrow1 = mrow0 + 8 * (size_t)L_;

    for (int kt = 0; kt < L_ / 64; kt++) {
        const int kj0 = kt * 64;
        const size_t ktok = (size_t)bb * L_ + kj0;
        __syncthreads();                       // prior PV done
        #pragma unroll
        for (int i = 0; i < 4; i++) {
            int id = tid + 256 * i;
            int r = id >> 4, dc = (id & 15) * 4;
            float4 kv = *(const float4*)&qkv[(ktok + r) * N3_ + 1024 + hc + dc];
            *(float4*)&Ks[r * 68 + dc] = kv;
            float4 vv = *(const float4*)&qkv[(ktok + r) * N3_ + 2048 + hc + dc];
            *(float4*)&Vs[r * 72 + dc] = vv;
        }
        __syncthreads();

        // S = Q @ K^T : warp m16 x n64, 8 k-steps
        float s[8][4];
        #pragma unroll
        for (int nt = 0; nt < 8; nt++)
            #pragma unroll
            for (int j = 0; j < 4; j++) s[nt][j] = 0.f;
        #pragma unroll
        for (int k8 = 0; k8 < 8; k8++) {
            const int kk = k8 * 8;
            uint32_t a[4];
            a[0] = __float_as_uint(Qs[(m0 + g    ) * 68 + kk + tg]);
            a[1] = __float_as_uint(Qs[(m0 + g + 8) * 68 + kk + tg]);
            a[2] = __float_as_uint(Qs[(m0 + g    ) * 68 + kk + tg + 4]);
            a[3] = __float_as_uint(Qs[(m0 + g + 8) * 68 + kk + tg + 4]);
            #pragma unroll
            for (int nt = 0; nt < 8; nt++) {
                uint32_t b[2];
                b[0] = __float_as_uint(Ks[(nt * 8 + g) * 68 + kk + tg]);
                b[1] = __float_as_uint(Ks[(nt * 8 + g) * 68 + kk + tg + 4]);
                mma8(s[nt], a, b);
            }
        }

        // scale + warp-local online softmax (rows g and g+8 of this warp)
        float r0 = -1e30f, r1 = -1e30f;
        #pragma unroll
        for (int nt = 0; nt < 8; nt++) {
            s[nt][0] *= 0.125f; s[nt][1] *= 0.125f;
            s[nt][2] *= 0.125f; s[nt][3] *= 0.125f;
            r0 = fmaxf(r0, fmaxf(s[nt][0], s[nt][1]));
            r1 = fmaxf(r1, fmaxf(s[nt][2], s[nt][3]));
        }
        r0 = fmaxf(r0, __shfl_xor_sync(0xffffffffu, r0, 1));
        r0 = fmaxf(r0, __shfl_xor_sync(0xffffffffu, r0, 2));
        r1 = fmaxf(r1, __shfl_xor_sync(0xffffffffu, r1, 1));
        r1 = fmaxf(r1, __shfl_xor_sync(0xffffffffu, r1, 2));

        float mn0 = fmaxf(mp0, r0), mn1 = fmaxf(mp1, r1);
        float c0 = fexp(mp0 - mn0), c1 = fexp(mp1 - mn1);
        mp0 = mn0; mp1 = mn1;

        float pe0 = 0.f, pe1 = 0.f, pm0 = 0.f, pm1 = 0.f;
        #pragma unroll
        for (int nt = 0; nt < 8; nt++) {
            const int mc = kj0 + nt * 8;
            float2 mk0 = *(const float2*)&mrow0[mc];
            float2 mk1 = *(const float2*)&mrow1[mc];
            float p00 = fexp(s[nt][0] - mn0);
            float p01 = fexp(s[nt][1] - mn0);
            float p10 = fexp(s[nt][2] - mn1);
            float p11 = fexp(s[nt][3] - mn1);
            pe0 += p00 + p01; pe1 += p10 + p11;
            float q00 = p00 * mk0.x, q01 = p01 * mk0.y;
            float q10 = p10 * mk1.x, q11 = p11 * mk1.y;
            pm0 += q00 + q01; pm1 += q10 + q11;
            *(float2*)&Ps[(m0 + g    ) * 68 + nt * 8 + 2 * tg] =
                make_float2(to_tf32(q00), to_tf32(q01));
            *(float2*)&Ps[(m0 + g + 8) * 68 + nt * 8 + 2 * tg] =
                make_float2(to_tf32(q10), to_tf32(q11));
        }
        pe0 += __shfl_xor_sync(0xffffffffu, pe0, 1);
        pe0 += __shfl_xor_sync(0xffffffffu, pe0, 2);
        pe1 += __shfl_xor_sync(0xffffffffu, pe1, 1);
        pe1 += __shfl_xor_sync(0xffffffffu, pe1, 2);
        pm0 += __shfl_xor_sync(0xffffffffu, pm0, 1);
        pm0 += __shfl_xor_sync(0xffffffffu, pm0, 2);
        pm1 += __shfl_xor_sync(0xffffffffu, pm1, 1);
        pm1 += __shfl_xor_sync(0xffffffffu, pm1, 2);
        se0 = se0 * c0 + pe0; se1 = se1 * c1 + pe1;
        sq0 = sq0 * c0 + pm0; sq1 = sq1 * c1 + pm1;
        #pragma unroll
        for (int nt = 0; nt < 8; nt++) {
            acc[nt][0] *= c0; acc[nt][1] *= c0;
            acc[nt][2] *= c1; acc[nt][3] *= c1;
        }
        __syncwarp();   // Ps is warp-private: warp-level fence suffices

        // acc += P @ V : m16 x n64(dh), k = 64 keys
        #pragma unroll
        for (int k8 = 0; k8 < 8; k8++) {
            const int kk = k8 * 8;
            uint32_t a[4];
            a[0] = __float_as_uint(Ps[(m0 + g    ) * 68 + kk + tg]);
            a[1] = __float_as_uint(Ps[(m0 + g + 8) * 68 + kk + tg]);
            a[2] = __float_as_uint(Ps[(m0 + g    ) * 68 + kk + tg + 4]);
            a[3] = __float_as_uint(Ps[(m0 + g + 8) * 68 + kk + tg + 4]);
            #pragma unroll
            for (int nt = 0; nt < 8; nt++) {
                uint32_t b[2];
                b[0] = __float_as_uint(Vs[(kk + tg    ) * 72 + nt * 8 + g]);
                b[1] = __float_as_uint(Vs[(kk + tg + 4) * 72 + nt * 8 + g]);
                mma8(acc[nt], a, b);
            }
        }
    }

    // epilogue: renorm, tf32-round for out-proj, write z[token][h*64+d]
    float inv0 = 1.0f / (sq0 + 1e-10f * se0 + 1e-30f);
    float inv1 = 1.0f / (sq1 + 1e-10f * se1 + 1e-30f);
    #pragma unroll
    for (int nt = 0; nt < 8; nt++) {
        int c = hc + nt * 8 + 2 * tg;
        *(float2*)&z[(tok0 + m0 + g) * D_ + c] =
            make_float2(to_tf32(acc[nt][0] * inv0), to_tf32(acc[nt][1] * inv0));
        *(float2*)&z[(tok0 + m0 + g + 8) * D_ + c] =
            make_float2(to_tf32(acc[nt][2] * inv1), to_tf32(acc[nt][3] * inv1));
    }
}

// ---------------------------------------------------------------------------
extern "C" void kernel_launch(void* const* d_in, const int* in_sizes, int n_in,
                              void* d_out, int out_size)
{
    const float* x    = (const float*)d_in[0];
    const float* mask = (const float*)d_in[1];
    const float* Wqkv = (const float*)d_in[2];
    const float* Wout = (const float*)d_in[3];
    const float* bout = (const float*)d_in[4];
    float* out = (float*)d_out;

    float *qkvp, *zp, *xr, *wq, *wo;
    cudaGetSymbolAddress((void**)&qkvp, g_qkv);
    cudaGetSymbolAddress((void**)&zp,   g_z);
    cudaGetSymbolAddress((void**)&xr,   g_xr);
    cudaGetSymbolAddress((void**)&wq,   g_wq);
    cudaGetSymbolAddress((void**)&wo,   g_wo);

    // 0) pre-round operands to tf32 (RNA — unbiased)
    {
        int n4x = MT_ * D_ / 4, n4q = D_ * N3_ / 4, n4o = D_ * D_ / 4;
        tf32_round<<<(n4x + 255) / 256, 256>>>((const float4*)x,    (float4*)xr, n4x);
        tf32_round<<<(n4q + 255) / 256, 256>>>((const float4*)Wqkv, (float4*)wq, n4q);
        tf32_round<<<(n4o + 255) / 256, 256>>>((const float4*)Wout, (float4*)wo, n4o);
    }

    // 1) QKV projection (outputs tf32-rounded for attention mma)
    mma_gemm<false, true><<<dim3(N3_ / 128, MT_ / 128), 256>>>(
        xr, wq, nullptr, qkvp, MT_, N3_, D_);

    // 2) masked flash attention (tf32 mma, outputs tf32-rounded z)
    cudaFuncSetAttribute(attn_mma, cudaFuncAttributeMaxDynamicSharedMemorySize,
                         ATTN_SMEM);
    attn_mma<<<dim3(L_ / 128, B_ * H_), 256, ATTN_SMEM>>>(qkvp, mask, zp);

    // 3) output projection + bias (exact fp32 output)
    mma_gemm<true, false><<<dim3(D_ / 128, MT_ / 128), 256>>>(
        zp, wo, bout, out, MT_, D_, D_);
}